// round 4
// baseline (speedup 1.0000x reference)
#include <cuda_runtime.h>
#include <cstddef>

#define BATCH 32
#define TQ 512
#define TK 2048
#define DIM 512

// 134 MB scratch for S / normalized P. Static __device__ array: the only
// allocation-rule-compliant scratch mechanism. Fully overwritten every call
// by gemm_qk, so kernel_launch stays deterministic.
__device__ float g_S[(size_t)BATCH * TQ * TK];

// ---------------------------------------------------------------------------
// Kernel 1: S[b,q,k] = sum_d Q[b,q,d] * E[b,k,d]   (NT SGEMM, both K-major)
// CTA tile 128x128, k-chunk (here: d-chunk) 16, 256 threads, 8x8 microtile.
// ---------------------------------------------------------------------------
__global__ __launch_bounds__(256, 2)
void gemm_qk_kernel(const float* __restrict__ Qg, const float* __restrict__ Eg)
{
    const int b  = blockIdx.z;
    const int q0 = blockIdx.y * 128;
    const int k0 = blockIdx.x * 128;

    const float* AG = Qg + (size_t)b * TQ * DIM;   // [512][512]
    const float* BG = Eg + (size_t)b * TK * DIM;   // [2048][512]
    float*       CG = g_S + (size_t)b * TQ * TK;   // [512][2048]

    __shared__ float As[2][16][128];
    __shared__ float Bs[2][16][128];

    const int tid = threadIdx.x;
    const int tx  = tid & 15;
    const int ty  = tid >> 4;

    // load mapping: tile row lr (0..127), float4-column pair lc (0/1)
    const int lr = tid & 127;
    const int lc = tid >> 7;

    const float* aptr = AG + (size_t)(q0 + lr) * DIM + lc * 4;
    const float* bptr = BG + (size_t)(k0 + lr) * DIM + lc * 4;

    float acc[8][8];
#pragma unroll
    for (int i = 0; i < 8; ++i)
#pragma unroll
        for (int j = 0; j < 8; ++j) acc[i][j] = 0.0f;

    // prologue: chunk 0 -> smem buf 0 (transposed store, conflict-free: bank = lr%32)
    {
        float4 a0 = *(const float4*)(aptr);
        float4 a1 = *(const float4*)(aptr + 8);
        float4 b0 = *(const float4*)(bptr);
        float4 b1 = *(const float4*)(bptr + 8);
        As[0][lc*4+0][lr] = a0.x; As[0][lc*4+1][lr] = a0.y;
        As[0][lc*4+2][lr] = a0.z; As[0][lc*4+3][lr] = a0.w;
        As[0][lc*4+8][lr] = a1.x; As[0][lc*4+9][lr] = a1.y;
        As[0][lc*4+10][lr] = a1.z; As[0][lc*4+11][lr] = a1.w;
        Bs[0][lc*4+0][lr] = b0.x; Bs[0][lc*4+1][lr] = b0.y;
        Bs[0][lc*4+2][lr] = b0.z; Bs[0][lc*4+3][lr] = b0.w;
        Bs[0][lc*4+8][lr] = b1.x; Bs[0][lc*4+9][lr] = b1.y;
        Bs[0][lc*4+10][lr] = b1.z; Bs[0][lc*4+11][lr] = b1.w;
    }
    __syncthreads();

    const int NK = DIM / 16;  // 32
    for (int kt = 0; kt < NK; ++kt) {
        const int buf = kt & 1;
        float4 na0 = make_float4(0,0,0,0), na1 = na0, nb0 = na0, nb1 = na0;
        const bool has_next = (kt + 1 < NK);
        if (has_next) {
            const float* ap = aptr + (kt + 1) * 16;
            const float* bp = bptr + (kt + 1) * 16;
            na0 = *(const float4*)(ap);
            na1 = *(const float4*)(ap + 8);
            nb0 = *(const float4*)(bp);
            nb1 = *(const float4*)(bp + 8);
        }
#pragma unroll
        for (int t = 0; t < 16; ++t) {
            float4 fa0 = *(const float4*)&As[buf][t][ty*4];
            float4 fa1 = *(const float4*)&As[buf][t][64 + ty*4];
            float4 fb0 = *(const float4*)&Bs[buf][t][tx*4];
            float4 fb1 = *(const float4*)&Bs[buf][t][64 + tx*4];
            float ar[8] = {fa0.x, fa0.y, fa0.z, fa0.w, fa1.x, fa1.y, fa1.z, fa1.w};
            float br[8] = {fb0.x, fb0.y, fb0.z, fb0.w, fb1.x, fb1.y, fb1.z, fb1.w};
#pragma unroll
            for (int i = 0; i < 8; ++i)
#pragma unroll
                for (int j = 0; j < 8; ++j)
                    acc[i][j] = fmaf(ar[i], br[j], acc[i][j]);
        }
        if (has_next) {
            const int nb = buf ^ 1;
            As[nb][lc*4+0][lr] = na0.x; As[nb][lc*4+1][lr] = na0.y;
            As[nb][lc*4+2][lr] = na0.z; As[nb][lc*4+3][lr] = na0.w;
            As[nb][lc*4+8][lr] = na1.x; As[nb][lc*4+9][lr] = na1.y;
            As[nb][lc*4+10][lr] = na1.z; As[nb][lc*4+11][lr] = na1.w;
            Bs[nb][lc*4+0][lr] = nb0.x; Bs[nb][lc*4+1][lr] = nb0.y;
            Bs[nb][lc*4+2][lr] = nb0.z; Bs[nb][lc*4+3][lr] = nb0.w;
            Bs[nb][lc*4+8][lr] = nb1.x; Bs[nb][lc*4+9][lr] = nb1.y;
            Bs[nb][lc*4+10][lr] = nb1.z; Bs[nb][lc*4+11][lr] = nb1.w;
        }
        __syncthreads();
    }

    // epilogue: float4 stores
#pragma unroll
    for (int ih = 0; ih < 2; ++ih) {
#pragma unroll
        for (int r = 0; r < 4; ++r) {
            const int row = q0 + ih * 64 + ty * 4 + r;
            const int ai  = ih * 4 + r;
            float4 o0 = make_float4(acc[ai][0], acc[ai][1], acc[ai][2], acc[ai][3]);
            float4 o1 = make_float4(acc[ai][4], acc[ai][5], acc[ai][6], acc[ai][7]);
            *(float4*)&CG[(size_t)row * TK + k0 + tx*4]      = o0;
            *(float4*)&CG[(size_t)row * TK + k0 + 64 + tx*4] = o1;
        }
    }
}

// ---------------------------------------------------------------------------
// Kernel 2: per-row softmax of S, written back in place as normalized P.
// One 256-thread CTA per (b,q) row; row lives in registers (8 floats/thread).
// ---------------------------------------------------------------------------
__global__ __launch_bounds__(256)
void softmax_rows_kernel()
{
    const int row = blockIdx.x;                          // 0 .. B*TQ-1
    float4* S4 = reinterpret_cast<float4*>(g_S) + (size_t)row * (TK / 4);
    const int tid = threadIdx.x;

    float4 v0 = S4[tid];
    float4 v1 = S4[tid + 256];

    float m = fmaxf(fmaxf(fmaxf(v0.x, v0.y), fmaxf(v0.z, v0.w)),
                    fmaxf(fmaxf(v1.x, v1.y), fmaxf(v1.z, v1.w)));
#pragma unroll
    for (int o = 16; o > 0; o >>= 1)
        m = fmaxf(m, __shfl_xor_sync(0xffffffffu, m, o));

    __shared__ float red_max[8];
    __shared__ float red_sum[8];
    if ((tid & 31) == 0) red_max[tid >> 5] = m;
    __syncthreads();
    m = fmaxf(fmaxf(fmaxf(red_max[0], red_max[1]), fmaxf(red_max[2], red_max[3])),
              fmaxf(fmaxf(red_max[4], red_max[5]), fmaxf(red_max[6], red_max[7])));

    float e[8];
    e[0] = __expf(v0.x - m); e[1] = __expf(v0.y - m);
    e[2] = __expf(v0.z - m); e[3] = __expf(v0.w - m);
    e[4] = __expf(v1.x - m); e[5] = __expf(v1.y - m);
    e[6] = __expf(v1.z - m); e[7] = __expf(v1.w - m);

    float s = ((e[0] + e[1]) + (e[2] + e[3])) + ((e[4] + e[5]) + (e[6] + e[7]));
#pragma unroll
    for (int o = 16; o > 0; o >>= 1)
        s += __shfl_xor_sync(0xffffffffu, s, o);
    if ((tid & 31) == 0) red_sum[tid >> 5] = s;
    __syncthreads();
    const float l = ((red_sum[0] + red_sum[1]) + (red_sum[2] + red_sum[3])) +
                    ((red_sum[4] + red_sum[5]) + (red_sum[6] + red_sum[7]));
    const float inv = 1.0f / l;

    v0 = make_float4(e[0]*inv, e[1]*inv, e[2]*inv, e[3]*inv);
    v1 = make_float4(e[4]*inv, e[5]*inv, e[6]*inv, e[7]*inv);
    S4[tid]       = v0;
    S4[tid + 256] = v1;
}

// ---------------------------------------------------------------------------
// Kernel 3: O[b,q,d] = sum_k P[b,q,k] * E[b,k,d]   (NN SGEMM)
// ---------------------------------------------------------------------------
__global__ __launch_bounds__(256, 2)
void gemm_av_kernel(const float* __restrict__ Eg, float* __restrict__ Og)
{
    const int b  = blockIdx.z;
    const int q0 = blockIdx.y * 128;
    const int d0 = blockIdx.x * 128;

    const float* AG = g_S + (size_t)b * TQ * TK;   // P [512][2048]
    const float* BG = Eg + (size_t)b * TK * DIM;   // [2048][512]
    float*       CG = Og + (size_t)b * TQ * DIM;   // [512][512]

    __shared__ float As[2][16][128];
    __shared__ float Bs[2][16][128];

    const int tid = threadIdx.x;
    const int tx  = tid & 15;
    const int ty  = tid >> 4;

    // A (P) loads: transposed store (reduction dim k is the inner dim)
    const int lr = tid & 127;
    const int lc = tid >> 7;
    const float* aptr = AG + (size_t)(q0 + lr) * TK + lc * 4;

    // B (E) loads: direct store (reduction dim k is the row dim)
    const int kr = tid >> 5;   // 0..7 (second float4 covers kr+8)
    const int c4 = tid & 31;
    const float* bptr = BG + (size_t)kr * DIM + d0 + c4 * 4;

    float acc[8][8];
#pragma unroll
    for (int i = 0; i < 8; ++i)
#pragma unroll
        for (int j = 0; j < 8; ++j) acc[i][j] = 0.0f;

    // prologue
    {
        float4 a0 = *(const float4*)(aptr);
        float4 a1 = *(const float4*)(aptr + 8);
        float4 b0 = *(const float4*)(bptr);
        float4 b1 = *(const float4*)(bptr + 8 * DIM);
        As[0][lc*4+0][lr] = a0.x; As[0][lc*4+1][lr] = a0.y;
        As[0][lc*4+2][lr] = a0.z; As[0][lc*4+3][lr] = a0.w;
        As[0][lc*4+8][lr] = a1.x; As[0][lc*4+9][lr] = a1.y;
        As[0][lc*4+10][lr] = a1.z; As[0][lc*4+11][lr] = a1.w;
        *(float4*)&Bs[0][kr][c4*4]     = b0;
        *(float4*)&Bs[0][kr + 8][c4*4] = b1;
    }
    __syncthreads();

    const int NK = TK / 16;  // 128
    for (int kt = 0; kt < NK; ++kt) {
        const int buf = kt & 1;
        float4 na0 = make_float4(0,0,0,0), na1 = na0, nb0 = na0, nb1 = na0;
        const bool has_next = (kt + 1 < NK);
        if (has_next) {
            const float* ap = aptr + (kt + 1) * 16;
            const float* bp = bptr + (size_t)(kt + 1) * 16 * DIM;
            na0 = *(const float4*)(ap);
            na1 = *(const float4*)(ap + 8);
            nb0 = *(const float4*)(bp);
            nb1 = *(const float4*)(bp + 8 * DIM);
        }
#pragma unroll
        for (int t = 0; t < 16; ++t) {
            float4 fa0 = *(const float4*)&As[buf][t][ty*4];
            float4 fa1 = *(const float4*)&As[buf][t][64 + ty*4];
            float4 fb0 = *(const float4*)&Bs[buf][t][tx*4];
            float4 fb1 = *(const float4*)&Bs[buf][t][64 + tx*4];
            float ar[8] = {fa0.x, fa0.y, fa0.z, fa0.w, fa1.x, fa1.y, fa1.z, fa1.w};
            float br[8] = {fb0.x, fb0.y, fb0.z, fb0.w, fb1.x, fb1.y, fb1.z, fb1.w};
#pragma unroll
            for (int i = 0; i < 8; ++i)
#pragma unroll
                for (int j = 0; j < 8; ++j)
                    acc[i][j] = fmaf(ar[i], br[j], acc[i][j]);
        }
        if (has_next) {
            const int nb = buf ^ 1;
            As[nb][lc*4+0][lr] = na0.x; As[nb][lc*4+1][lr] = na0.y;
            As[nb][lc*4+2][lr] = na0.z; As[nb][lc*4+3][lr] = na0.w;
            As[nb][lc*4+8][lr] = na1.x; As[nb][lc*4+9][lr] = na1.y;
            As[nb][lc*4+10][lr] = na1.z; As[nb][lc*4+11][lr] = na1.w;
            *(float4*)&Bs[nb][kr][c4*4]     = nb0;
            *(float4*)&Bs[nb][kr + 8][c4*4] = nb1;
        }
        __syncthreads();
    }

#pragma unroll
    for (int ih = 0; ih < 2; ++ih) {
#pragma unroll
        for (int r = 0; r < 4; ++r) {
            const int row = q0 + ih * 64 + ty * 4 + r;
            const int ai  = ih * 4 + r;
            float4 o0 = make_float4(acc[ai][0], acc[ai][1], acc[ai][2], acc[ai][3]);
            float4 o1 = make_float4(acc[ai][4], acc[ai][5], acc[ai][6], acc[ai][7]);
            *(float4*)&CG[(size_t)row * DIM + d0 + tx*4]      = o0;
            *(float4*)&CG[(size_t)row * DIM + d0 + 64 + tx*4] = o1;
        }
    }
}

// ---------------------------------------------------------------------------
// kernel_launch: Q = d_in[0] (32,512,512), E = d_in[1] (32,2048,512), fp32 out.
// Three launches on the capture stream; graph-capturable, allocation-free.
// ---------------------------------------------------------------------------
extern "C" void kernel_launch(void* const* d_in, const int* in_sizes, int n_in,
                              void* d_out, int out_size)
{
    (void)in_sizes; (void)n_in; (void)out_size;
    const float* Q = (const float*)d_in[0];
    const float* E = (const float*)d_in[1];
    float* O = (float*)d_out;

    dim3 g1(TK / 128, TQ / 128, BATCH);   // (16, 4, 32)
    gemm_qk_kernel<<<g1, 256>>>(Q, E);

    softmax_rows_kernel<<<BATCH * TQ, 256>>>();

    dim3 g3(DIM / 128, TQ / 128, BATCH);  // (4, 4, 32)
    gemm_av_kernel<<<g3, 256>>>(E, O);
}